// round 16
// baseline (speedup 1.0000x reference)
#include <cuda_runtime.h>
#include <cuda_fp16.h>
#include <stdint.h>

#define SEQT 512
#define NB   16
#define NT   512

#define S0   224    // layer0 B row stride bytes (K=96 -> 6x32B groups + pad)
#define S1   160    // layer1 B row stride bytes (h1 only: 4x32B groups + pad)

// dynamic SMEM map (bytes)
#define OFF_B0   0                      // 2 parities x 16*224 = 7168
#define OFF_B1   7168                   // 2 parities x 16*160 = 5120
#define SMEM_TOTAL 12288

__device__ __forceinline__ void mma_f16(float c[4], const uint32_t a[4],
                                        uint32_t b0, uint32_t b1) {
    asm volatile(
        "mma.sync.aligned.m16n8k16.row.col.f32.f16.f16.f32 "
        "{%0,%1,%2,%3}, {%4,%5,%6,%7}, {%8,%9}, {%0,%1,%2,%3};"
        : "+f"(c[0]), "+f"(c[1]), "+f"(c[2]), "+f"(c[3])
        : "r"(a[0]), "r"(a[1]), "r"(a[2]), "r"(a[3]), "r"(b0), "r"(b1));
}

__device__ __forceinline__ float tanha(float x) {
    float r; asm("tanh.approx.f32 %0, %1;" : "=f"(r) : "f"(x)); return r;
}
__device__ __forceinline__ float sigf(float x) { return fmaf(tanha(0.5f * x), 0.5f, 0.5f); }

// byte offset of (batch n, k) in fp16 B buffer
// 32B group per 16 k; 8B unit per tq: [k(2t), k(2t+1), k(2t+8), k(2t+9)]
__device__ __forceinline__ int boff(int n, int k, int S) {
    return n * S + (k >> 4) * 32 + ((k >> 1) & 3) * 8 + ((k >> 3) & 1) * 4 + (k & 1) * 2;
}

__global__ void __launch_bounds__(NT, 1)
lstm_fused(const float* __restrict__ x,
           const float* __restrict__ W_ih0, const float* __restrict__ W_hh0,
           const float* __restrict__ b_ih0, const float* __restrict__ b_hh0,
           const float* __restrict__ W_ih1, const float* __restrict__ W_hh1,
           const float* __restrict__ b_ih1, const float* __restrict__ b_hh1,
           const float* __restrict__ ln_g, const float* __restrict__ ln_b,
           const float* __restrict__ fc_w, const float* __restrict__ fc_b,
           float* __restrict__ out)
{
    extern __shared__ __align__(16) unsigned char sm[];
    const int tid  = threadIdx.x;
    const int w    = tid >> 5;
    const int lane = tid & 31;
    const int g    = lane >> 2;
    const int tq   = lane & 3;
    const int role = w >> 3;          // 0: layer0 warps, 1: layer1 warps
    const int jv   = 8 * (w & 7) + g; // cell index this thread owns
    const int b0   = blockIdx.x * NB;

    // zero B buffers (both parities)
    for (int i = tid; i < SMEM_TOTAL / 4; i += NT) ((uint32_t*)sm)[i] = 0;

    // ---- A fragments: my layer only, full K, fp16 in regs ----
    uint32_t A[2][8][4];
    if (role == 0) {
        #pragma unroll
        for (int tile = 0; tile < 2; tile++)
            #pragma unroll
            for (int kt = 0; kt < 6; kt++)
                #pragma unroll
                for (int i = 0; i < 4; i++) {
                    int m = tile * 128 + (i & 1) * 64 + jv;
                    int k = 16 * kt + 2 * tq + (i >> 1) * 8;
                    float v0 = (k < 32)     ? W_ih0[m * 32 + k]     : W_hh0[m * 64 + k - 32];
                    float v1 = (k + 1 < 32) ? W_ih0[m * 32 + k + 1] : W_hh0[m * 64 + k + 1 - 32];
                    uint16_t h0 = __half_as_ushort(__float2half_rn(v0));
                    uint16_t h1 = __half_as_ushort(__float2half_rn(v1));
                    A[tile][kt][i] = (uint32_t)h0 | ((uint32_t)h1 << 16);
                }
    } else {
        #pragma unroll
        for (int tile = 0; tile < 2; tile++)
            #pragma unroll
            for (int kt = 0; kt < 8; kt++)
                #pragma unroll
                for (int i = 0; i < 4; i++) {
                    int m = tile * 128 + (i & 1) * 64 + jv;
                    int k = 16 * kt + 2 * tq + (i >> 1) * 8;
                    float v0 = (k < 64)     ? W_ih1[m * 64 + k]     : W_hh1[m * 64 + k - 64];
                    float v1 = (k + 1 < 64) ? W_ih1[m * 64 + k + 1] : W_hh1[m * 64 + k + 1 - 64];
                    uint16_t h0 = __half_as_ushort(__float2half_rn(v0));
                    uint16_t h1 = __half_as_ushort(__float2half_rn(v1));
                    A[tile][kt][i] = (uint32_t)h0 | ((uint32_t)h1 << 16);
                }
    }

    float bias[4];
    #pragma unroll
    for (int q = 0; q < 4; q++) {
        bias[q] = role ? (b_ih1[q * 64 + jv] + b_hh1[q * 64 + jv])
                       : (b_ih0[q * 64 + jv] + b_hh0[q * 64 + jv]);
    }

    // x(0) -> B0 parity 0 (warp = batch row, lane = k)
    {
        float xv = x[((size_t)(b0 + w) * SEQT) * 32 + lane];
        *(uint16_t*)(sm + OFF_B0 + boff(w, lane, S0)) =
            __half_as_ushort(__float2half_rn(xv));
    }
    __syncthreads();

    float cs[2][2] = {{0, 0}, {0, 0}};      // my layer's c-state [nt][d], fp32
    float h1fin[2][2] = {{0, 0}, {0, 0}};   // layer1 warps: final h (fp32)

    // ---------- role bodies ----------
    // C accumulators start at bias (MMA accumulates on top).
    auto init_C = [&](float C[2][2][4]) {
        #pragma unroll
        for (int nt = 0; nt < 2; nt++) {
            C[0][nt][0] = bias[0]; C[0][nt][1] = bias[0];
            C[0][nt][2] = bias[1]; C[0][nt][3] = bias[1];
            C[1][nt][0] = bias[2]; C[1][nt][1] = bias[2];
            C[1][nt][2] = bias[3]; C[1][nt][3] = bias[3];
        }
    };

    auto l0_phase = [&](const unsigned char* B0r, unsigned char* B0w) {
        float C[2][2][4];
        init_C(C);
        #pragma unroll
        for (int kt = 0; kt < 6; kt++) {
            #pragma unroll
            for (int nt = 0; nt < 2; nt++) {
                uint2 v = *(const uint2*)(B0r + (8 * nt + g) * S0 + kt * 32 + tq * 8);
                mma_f16(C[0][nt], A[0][kt], v.x, v.y);
                mma_f16(C[1][nt], A[1][kt], v.x, v.y);
            }
        }
        #pragma unroll
        for (int nt = 0; nt < 2; nt++)
            #pragma unroll
            for (int d = 0; d < 2; d++) {
                float ig = sigf(C[0][nt][d]);
                float fg = sigf(C[0][nt][2 + d]);
                float gg = tanha(C[1][nt][d]);
                float og = sigf(C[1][nt][2 + d]);
                float c = fg * cs[nt][d] + ig * gg;
                cs[nt][d] = c;
                float h = og * tanha(c);
                int b = 8 * nt + 2 * tq + d;
                *(uint16_t*)(B0w + boff(b, 32 + jv, S0)) =
                    __half_as_ushort(__float2half_rn(h));   // layer0 recurrence (L1 reads here too)
            }
    };
    // layer1: h0 read straight from B0r's h-region (groups 2-5); h1 from B1r
    auto l1_phase = [&](const unsigned char* B0r, const unsigned char* B1r,
                        unsigned char* B1w) {
        float C[2][2][4];
        init_C(C);
        #pragma unroll
        for (int kt = 0; kt < 4; kt++) {
            #pragma unroll
            for (int nt = 0; nt < 2; nt++) {
                uint2 v = *(const uint2*)(B0r + (8 * nt + g) * S0 + (kt + 2) * 32 + tq * 8);
                mma_f16(C[0][nt], A[0][kt], v.x, v.y);
                mma_f16(C[1][nt], A[1][kt], v.x, v.y);
            }
        }
        #pragma unroll
        for (int kt = 4; kt < 8; kt++) {
            #pragma unroll
            for (int nt = 0; nt < 2; nt++) {
                uint2 v = *(const uint2*)(B1r + (8 * nt + g) * S1 + (kt - 4) * 32 + tq * 8);
                mma_f16(C[0][nt], A[0][kt], v.x, v.y);
                mma_f16(C[1][nt], A[1][kt], v.x, v.y);
            }
        }
        #pragma unroll
        for (int nt = 0; nt < 2; nt++)
            #pragma unroll
            for (int d = 0; d < 2; d++) {
                float ig = sigf(C[0][nt][d]);
                float fg = sigf(C[0][nt][2 + d]);
                float gg = tanha(C[1][nt][d]);
                float og = sigf(C[1][nt][2 + d]);
                float c = fg * cs[nt][d] + ig * gg;
                cs[nt][d] = c;
                float h = og * tanha(c);
                h1fin[nt][d] = h;
                int b = 8 * nt + 2 * tq + d;
                *(uint16_t*)(B1w + boff(b, jv, S1)) =
                    __half_as_ushort(__float2half_rn(h));   // layer1 recurrence
            }
    };

    // ---------- p = 0 (layer0 warps compute; L0 warps also store x(1)) ----------
    {
        if (role == 0) {
            float xn0 = x[((size_t)(b0 + w) * SEQT + 1) * 32 + lane];
            float xn1 = x[((size_t)(b0 + w + 8) * SEQT + 1) * 32 + lane];
            l0_phase(sm + OFF_B0, sm + OFF_B0 + NB * S0);
            *(uint16_t*)(sm + OFF_B0 + NB * S0 + boff(w, lane, S0)) =
                __half_as_ushort(__float2half_rn(xn0));
            *(uint16_t*)(sm + OFF_B0 + NB * S0 + boff(w + 8, lane, S0)) =
                __half_as_ushort(__float2half_rn(xn1));
        }
        __syncthreads();
    }

    // ---------- main loop p = 1 .. SEQT-1 ----------
    #pragma unroll 1
    for (int p = 1; p < SEQT; p++) {
        const int par = p & 1;
        const unsigned char* B0r = sm + OFF_B0 + par * (NB * S0);
        const unsigned char* B1r = sm + OFF_B1 + par * (NB * S1);
        unsigned char* B0w = sm + OFF_B0 + (par ^ 1) * (NB * S0);
        unsigned char* B1w = sm + OFF_B1 + (par ^ 1) * (NB * S1);

        if (role == 0) {
            float xn0 = 0.0f, xn1 = 0.0f;
            if (p + 1 < SEQT) {
                xn0 = x[((size_t)(b0 + w) * SEQT + (p + 1)) * 32 + lane];
                xn1 = x[((size_t)(b0 + w + 8) * SEQT + (p + 1)) * 32 + lane];
            }
            l0_phase(B0r, B0w);
            if (p + 1 < SEQT) {
                *(uint16_t*)(B0w + boff(w, lane, S0)) =
                    __half_as_ushort(__float2half_rn(xn0));
                *(uint16_t*)(B0w + boff(w + 8, lane, S0)) =
                    __half_as_ushort(__float2half_rn(xn1));
            }
        } else {
            l1_phase(B0r, B1r, B1w);
        }
        __syncthreads();
    }

    // ---------- p = SEQT (layer1 warps only, t = SEQT-1) ----------
    {
        // par(SEQT)=0: h0(511) in B0 parity0, h1(510) in B1 parity0
        if (role == 1)
            l1_phase(sm + OFF_B0, sm + OFF_B1, sm + OFF_B1 + NB * S1);
        __syncthreads();
    }

    // ---- LayerNorm + FC on h1(T-1) ----
    float* hb = (float*)(sm + OFF_B0);    // reuse B0 area
    if (role == 1) {
        #pragma unroll
        for (int nt = 0; nt < 2; nt++)
            #pragma unroll
            for (int d = 0; d < 2; d++) {
                int b = 8 * nt + 2 * tq + d;
                hb[b * 64 + jv] = h1fin[nt][d];
            }
    }
    __syncthreads();
    if (tid < NB) {
        const float* h = hb + tid * 64;
        float mu = 0.0f;
        #pragma unroll
        for (int j = 0; j < 64; j++) mu += h[j];
        mu *= (1.0f / 64.0f);
        float var = 0.0f;
        #pragma unroll
        for (int j = 0; j < 64; j++) { float dd = h[j] - mu; var += dd * dd; }
        var *= (1.0f / 64.0f);
        float rstd = rsqrtf(var + 1e-5f);
        float sacc = 0.0f;
        #pragma unroll
        for (int j = 0; j < 64; j++)
            sacc += ((h[j] - mu) * rstd * ln_g[j] + ln_b[j]) * fc_w[j];
        out[b0 + tid] = sacc + fc_b[0];
    }
}

extern "C" void kernel_launch(void* const* d_in, const int* in_sizes, int n_in,
                              void* d_out, int out_size)
{
    const float* x     = (const float*)d_in[0];
    const float* W_ih0 = (const float*)d_in[1];
    const float* W_hh0 = (const float*)d_in[2];
    const float* b_ih0 = (const float*)d_in[3];
    const float* b_hh0 = (const float*)d_in[4];
    const float* W_ih1 = (const float*)d_in[5];
    const float* W_hh1 = (const float*)d_in[6];
    const float* b_ih1 = (const float*)d_in[7];
    const float* b_hh1 = (const float*)d_in[8];
    const float* ln_g  = (const float*)d_in[9];
    const float* ln_b  = (const float*)d_in[10];
    const float* fc_w  = (const float*)d_in[11];
    const float* fc_b  = (const float*)d_in[12];
    float* out = (float*)d_out;

    cudaFuncSetAttribute(lstm_fused, cudaFuncAttributeMaxDynamicSharedMemorySize, SMEM_TOTAL);
    lstm_fused<<<2048 / NB, NT, SMEM_TOTAL>>>(x, W_ih0, W_hh0, b_ih0, b_hh0,
                                              W_ih1, W_hh1, b_ih1, b_hh1,
                                              ln_g, ln_b, fc_w, fc_b, out);
}

// round 17
// speedup vs baseline: 1.0443x; 1.0443x over previous
#include <cuda_runtime.h>
#include <cuda_fp16.h>
#include <stdint.h>

#define SEQT 512
#define NB   16
#define NT   512

#define S0   224    // layer0 B row stride bytes (K=96 -> 6x32B groups + pad)
#define S1   160    // layer1 B row stride bytes (h1 only: 4x32B groups + pad)

#define B0SLOT (NB * S0)                // 3584
#define B1PAR  (NB * S1)                // 2560
#define OFF_B0 0                        // 3 slots x 3584 = 10752
#define OFF_B1 10752                    // 2 parities x 2560 = 5120
#define SMEM_TOTAL 16384

// named barrier ids: 1 = L0 internal, 2 = L1 internal, 3..5 = F[slot], 6..8 = Bk[slot]
#define BAR_SYNC(id, cnt)   asm volatile("bar.sync %0, %1;"   :: "r"(id), "r"(cnt) : "memory")
#define BAR_ARRIVE(id, cnt) asm volatile("bar.arrive %0, %1;" :: "r"(id), "r"(cnt) : "memory")

__device__ __forceinline__ void mma_f16(float c[4], const uint32_t a[4],
                                        uint32_t b0, uint32_t b1) {
    asm volatile(
        "mma.sync.aligned.m16n8k16.row.col.f32.f16.f16.f32 "
        "{%0,%1,%2,%3}, {%4,%5,%6,%7}, {%8,%9}, {%0,%1,%2,%3};"
        : "+f"(c[0]), "+f"(c[1]), "+f"(c[2]), "+f"(c[3])
        : "r"(a[0]), "r"(a[1]), "r"(a[2]), "r"(a[3]), "r"(b0), "r"(b1));
}

__device__ __forceinline__ float tanha(float x) {
    float r; asm("tanh.approx.f32 %0, %1;" : "=f"(r) : "f"(x)); return r;
}
__device__ __forceinline__ float sigf(float x) { return fmaf(tanha(0.5f * x), 0.5f, 0.5f); }

// byte offset of (batch n, k) in fp16 B buffer
// 32B group per 16 k; 8B unit per tq: [k(2t), k(2t+1), k(2t+8), k(2t+9)]
__device__ __forceinline__ int boff(int n, int k, int S) {
    return n * S + (k >> 4) * 32 + ((k >> 1) & 3) * 8 + ((k >> 3) & 1) * 4 + (k & 1) * 2;
}

__global__ void __launch_bounds__(NT, 1)
lstm_fused(const float* __restrict__ x,
           const float* __restrict__ W_ih0, const float* __restrict__ W_hh0,
           const float* __restrict__ b_ih0, const float* __restrict__ b_hh0,
           const float* __restrict__ W_ih1, const float* __restrict__ W_hh1,
           const float* __restrict__ b_ih1, const float* __restrict__ b_hh1,
           const float* __restrict__ ln_g, const float* __restrict__ ln_b,
           const float* __restrict__ fc_w, const float* __restrict__ fc_b,
           float* __restrict__ out)
{
    extern __shared__ __align__(16) unsigned char sm[];
    const int tid  = threadIdx.x;
    const int w    = tid >> 5;
    const int lane = tid & 31;
    const int g    = lane >> 2;
    const int tq   = lane & 3;
    const int role = w >> 3;          // 0: layer0 warps, 1: layer1 warps
    const int jv   = 8 * (w & 7) + g; // cell index this thread owns
    const int b0   = blockIdx.x * NB;

    // zero all buffers
    for (int i = tid; i < SMEM_TOTAL / 4; i += NT) ((uint32_t*)sm)[i] = 0;

    // ---- A fragments: my layer only, full K, fp16 in regs ----
    uint32_t A[2][8][4];
    if (role == 0) {
        #pragma unroll
        for (int tile = 0; tile < 2; tile++)
            #pragma unroll
            for (int kt = 0; kt < 6; kt++)
                #pragma unroll
                for (int i = 0; i < 4; i++) {
                    int m = tile * 128 + (i & 1) * 64 + jv;
                    int k = 16 * kt + 2 * tq + (i >> 1) * 8;
                    float v0 = (k < 32)     ? W_ih0[m * 32 + k]     : W_hh0[m * 64 + k - 32];
                    float v1 = (k + 1 < 32) ? W_ih0[m * 32 + k + 1] : W_hh0[m * 64 + k + 1 - 32];
                    uint16_t h0 = __half_as_ushort(__float2half_rn(v0));
                    uint16_t h1 = __half_as_ushort(__float2half_rn(v1));
                    A[tile][kt][i] = (uint32_t)h0 | ((uint32_t)h1 << 16);
                }
    } else {
        #pragma unroll
        for (int tile = 0; tile < 2; tile++)
            #pragma unroll
            for (int kt = 0; kt < 8; kt++)
                #pragma unroll
                for (int i = 0; i < 4; i++) {
                    int m = tile * 128 + (i & 1) * 64 + jv;
                    int k = 16 * kt + 2 * tq + (i >> 1) * 8;
                    float v0 = (k < 64)     ? W_ih1[m * 64 + k]     : W_hh1[m * 64 + k - 64];
                    float v1 = (k + 1 < 64) ? W_ih1[m * 64 + k + 1] : W_hh1[m * 64 + k + 1 - 64];
                    uint16_t h0 = __half_as_ushort(__float2half_rn(v0));
                    uint16_t h1 = __half_as_ushort(__float2half_rn(v1));
                    A[tile][kt][i] = (uint32_t)h0 | ((uint32_t)h1 << 16);
                }
    }

    float bias[4];
    #pragma unroll
    for (int q = 0; q < 4; q++) {
        bias[q] = role ? (b_ih1[q * 64 + jv] + b_hh1[q * 64 + jv])
                       : (b_ih0[q * 64 + jv] + b_hh0[q * 64 + jv]);
    }

    // x(0) -> B0 slot 2 (L0@0 reads slot (0-1)%3 = 2); all warps, 1 row each
    {
        float xv = x[((size_t)(b0 + w) * SEQT) * 32 + lane];
        *(uint16_t*)(sm + OFF_B0 + 2 * B0SLOT + boff(w, lane, S0)) =
            __half_as_ushort(__float2half_rn(xv));
    }
    __syncthreads();

    float cs[2][2] = {{0, 0}, {0, 0}};      // my layer's c-state [nt][d], fp32
    float h1fin[2][2] = {{0, 0}, {0, 0}};   // layer1 warps: final h (fp32)

    auto init_C = [&](float C[2][2][4]) {
        #pragma unroll
        for (int nt = 0; nt < 2; nt++) {
            C[0][nt][0] = bias[0]; C[0][nt][1] = bias[0];
            C[0][nt][2] = bias[1]; C[0][nt][3] = bias[1];
            C[1][nt][0] = bias[2]; C[1][nt][1] = bias[2];
            C[1][nt][2] = bias[3]; C[1][nt][3] = bias[3];
        }
    };

    if (role == 0) {
        // ================= LAYER 0 producer =================
        int sw = 0;                       // write slot = p % 3
        int sr = 2;                       // read slot  = (p-1) % 3
        #pragma unroll 1
        for (int p = 0; p < SEQT; p++) {
            const unsigned char* Br = sm + OFF_B0 + sr * B0SLOT;
            unsigned char* Bw = sm + OFF_B0 + sw * B0SLOT;

            float xn0 = 0.0f, xn1 = 0.0f;
            if (p + 1 < SEQT) {
                xn0 = x[((size_t)(b0 + w) * SEQT + (p + 1)) * 32 + lane];
                xn1 = x[((size_t)(b0 + w + 8) * SEQT + (p + 1)) * 32 + lane];
            }

            float C[2][2][4];
            init_C(C);
            #pragma unroll
            for (int kt = 0; kt < 6; kt++) {
                #pragma unroll
                for (int nt = 0; nt < 2; nt++) {
                    uint2 v = *(const uint2*)(Br + (8 * nt + g) * S0 + kt * 32 + tq * 8);
                    mma_f16(C[0][nt], A[0][kt], v.x, v.y);
                    mma_f16(C[1][nt], A[1][kt], v.x, v.y);
                }
            }
            float hv[2][2];
            #pragma unroll
            for (int nt = 0; nt < 2; nt++)
                #pragma unroll
                for (int d = 0; d < 2; d++) {
                    float ig = sigf(C[0][nt][d]);
                    float fg = sigf(C[0][nt][2 + d]);
                    float gg = tanha(C[1][nt][d]);
                    float og = sigf(C[1][nt][2 + d]);
                    float c = fg * cs[nt][d] + ig * gg;
                    cs[nt][d] = c;
                    hv[nt][d] = og * tanha(c);
                }

            BAR_SYNC(6 + sw, 512);        // wait: L1 done reading this slot
            #pragma unroll
            for (int nt = 0; nt < 2; nt++)
                #pragma unroll
                for (int d = 0; d < 2; d++) {
                    int b = 8 * nt + 2 * tq + d;
                    *(uint16_t*)(Bw + boff(b, 32 + jv, S0)) =
                        __half_as_ushort(__float2half_rn(hv[nt][d]));
                }
            if (p + 1 < SEQT) {
                *(uint16_t*)(Bw + boff(w, lane, S0)) =
                    __half_as_ushort(__float2half_rn(xn0));
                *(uint16_t*)(Bw + boff(w + 8, lane, S0)) =
                    __half_as_ushort(__float2half_rn(xn1));
            }
            BAR_SYNC(1, 256);             // L0 internal (writes visible to L0 + drained)
            BAR_ARRIVE(3 + sw, 512);      // publish h0(p)

            sr = sw;
            sw = (sw == 2) ? 0 : sw + 1;
        }
    } else {
        // ================= LAYER 1 consumer =================
        BAR_ARRIVE(6, 512);               // prime backward semaphores
        BAR_ARRIVE(7, 512);
        BAR_ARRIVE(8, 512);
        int slot = 0;                     // = (q-1) % 3
        #pragma unroll 1
        for (int q = 1; q <= SEQT; q++) {
            const unsigned char* B0r = sm + OFF_B0 + slot * B0SLOT;
            const unsigned char* B1r = sm + OFF_B1 + (q & 1) * B1PAR;
            unsigned char* B1w = sm + OFF_B1 + ((q & 1) ^ 1) * B1PAR;

            BAR_SYNC(3 + slot, 512);      // wait: h0(q-1) published

            float C[2][2][4];
            init_C(C);
            #pragma unroll
            for (int kt = 0; kt < 4; kt++) {
                #pragma unroll
                for (int nt = 0; nt < 2; nt++) {
                    uint2 v = *(const uint2*)(B0r + (8 * nt + g) * S0 + (kt + 2) * 32 + tq * 8);
                    mma_f16(C[0][nt], A[0][kt], v.x, v.y);
                    mma_f16(C[1][nt], A[1][kt], v.x, v.y);
                }
            }
            #pragma unroll
            for (int kt = 4; kt < 8; kt++) {
                #pragma unroll
                for (int nt = 0; nt < 2; nt++) {
                    uint2 v = *(const uint2*)(B1r + (8 * nt + g) * S1 + (kt - 4) * 32 + tq * 8);
                    mma_f16(C[0][nt], A[0][kt], v.x, v.y);
                    mma_f16(C[1][nt], A[1][kt], v.x, v.y);
                }
            }
            BAR_ARRIVE(6 + slot, 512);    // slot consumed; L0 may overwrite

            #pragma unroll
            for (int nt = 0; nt < 2; nt++)
                #pragma unroll
                for (int d = 0; d < 2; d++) {
                    float ig = sigf(C[0][nt][d]);
                    float fg = sigf(C[0][nt][2 + d]);
                    float gg = tanha(C[1][nt][d]);
                    float og = sigf(C[1][nt][2 + d]);
                    float c = fg * cs[nt][d] + ig * gg;
                    cs[nt][d] = c;
                    float h = og * tanha(c);
                    h1fin[nt][d] = h;
                    int b = 8 * nt + 2 * tq + d;
                    *(uint16_t*)(B1w + boff(b, jv, S1)) =
                        __half_as_ushort(__float2half_rn(h));
                }
            BAR_SYNC(2, 256);             // L1 internal

            slot = (slot == 2) ? 0 : slot + 1;
        }
    }

    __syncthreads();

    // ---- LayerNorm + FC on h1(T-1) ----
    float* hb = (float*)(sm + OFF_B0);    // reuse B0 area
    if (role == 1) {
        #pragma unroll
        for (int nt = 0; nt < 2; nt++)
            #pragma unroll
            for (int d = 0; d < 2; d++) {
                int b = 8 * nt + 2 * tq + d;
                hb[b * 64 + jv] = h1fin[nt][d];
            }
    }
    __syncthreads();
    if (tid < NB) {
        const float* h = hb + tid * 64;
        float mu = 0.0f;
        #pragma unroll
        for (int j = 0; j < 64; j++) mu += h[j];
        mu *= (1.0f / 64.0f);
        float var = 0.0f;
        #pragma unroll
        for (int j = 0; j < 64; j++) { float dd = h[j] - mu; var += dd * dd; }
        var *= (1.0f / 64.0f);
        float rstd = rsqrtf(var + 1e-5f);
        float sacc = 0.0f;
        #pragma unroll
        for (int j = 0; j < 64; j++)
            sacc += ((h[j] - mu) * rstd * ln_g[j] + ln_b[j]) * fc_w[j];
        out[b0 + tid] = sacc + fc_b[0];
    }
}

extern "C" void kernel_launch(void* const* d_in, const int* in_sizes, int n_in,
                              void* d_out, int out_size)
{
    const float* x     = (const float*)d_in[0];
    const float* W_ih0 = (const float*)d_in[1];
    const float* W_hh0 = (const float*)d_in[2];
    const float* b_ih0 = (const float*)d_in[3];
    const float* b_hh0 = (const float*)d_in[4];
    const float* W_ih1 = (const float*)d_in[5];
    const float* W_hh1 = (const float*)d_in[6];
    const float* b_ih1 = (const float*)d_in[7];
    const float* b_hh1 = (const float*)d_in[8];
    const float* ln_g  = (const float*)d_in[9];
    const float* ln_b  = (const float*)d_in[10];
    const float* fc_w  = (const float*)d_in[11];
    const float* fc_b  = (const float*)d_in[12];
    float* out = (float*)d_out;

    cudaFuncSetAttribute(lstm_fused, cudaFuncAttributeMaxDynamicSharedMemorySize, SMEM_TOTAL);
    lstm_fused<<<2048 / NB, NT, SMEM_TOTAL>>>(x, W_ih0, W_hh0, b_ih0, b_hh0,
                                              W_ih1, W_hh1, b_ih1, b_hh1,
                                              ln_g, ln_b, fc_w, fc_b, out);
}